// round 15
// baseline (speedup 1.0000x reference)
#include <cuda_runtime.h>
#include <cuda_bf16.h>
#include <cuda_fp16.h>
#include <math.h>
#include <stdint.h>

// ---------------- problem constants ----------------
#define BATCH 4
#define SEQ   4096
#define DIM   1024
#define HEADS 16
#define HD    64
#define WIN   128
#define NW    (SEQ / WIN)         // 32
#define MROWS (BATCH * SEQ)       // 16384
#define HIDDEN 2048               // = 2*DIM
#define FF1N  (2 * HIDDEN)        // 4096

// ---------------- scratch (device globals; allocation-free) ----------------
static __device__ __align__(128) float g_x1  [(size_t)MROWS * DIM];

static __device__ __align__(128) __half g_lnh [(size_t)MROWS * DIM];
static __device__ __align__(128) __half g_ath [(size_t)MROWS * DIM];
static __device__ __align__(128) __half g_hh  [(size_t)MROWS * HIDDEN];
static __device__ __align__(128) __half g_qkvh[(size_t)3 * MROWS * DIM];

// transposed fp16 weights [N][K] K-major
#define WT_TOTAL (10u * 1024u * 1024u)
static __device__ __align__(128) __half g_wt[WT_TOTAL];

// ================= helpers =================
__device__ __forceinline__ uint32_t smem_u32(const void* p) {
    uint32_t a;
    asm("{ .reg .u64 t; cvta.to.shared.u64 t, %1; cvt.u32.u64 %0, t; }" : "=r"(a) : "l"(p));
    return a;
}

#define CP_ASYNC16(dst, src) \
    asm volatile("cp.async.cg.shared.global [%0], [%1], 16;" :: "r"(dst), "l"(src))
#define CP_COMMIT() asm volatile("cp.async.commit_group;" ::: "memory")
#define CP_WAIT4()  asm volatile("cp.async.wait_group 4;" ::: "memory")
#define CP_WAIT2()  asm volatile("cp.async.wait_group 2;" ::: "memory")
#define CP_WAIT1()  asm volatile("cp.async.wait_group 1;" ::: "memory")
#define CP_WAIT0()  asm volatile("cp.async.wait_group 0;" ::: "memory")

#define LDSM_X4(r0, r1, r2, r3, addr) \
    asm volatile("ldmatrix.sync.aligned.m8n8.x4.shared.b16 {%0,%1,%2,%3}, [%4];" \
        : "=r"(r0), "=r"(r1), "=r"(r2), "=r"(r3) : "r"(addr))

#define LDSM_X4_TRANS(r0, r1, r2, r3, addr) \
    asm volatile("ldmatrix.sync.aligned.m8n8.x4.trans.shared.b16 {%0,%1,%2,%3}, [%4];" \
        : "=r"(r0), "=r"(r1), "=r"(r2), "=r"(r3) : "r"(addr))

#define MMA16816(d, a, b) \
    asm volatile("mma.sync.aligned.m16n8k16.row.col.f32.f16.f16.f32 " \
        "{%0,%1,%2,%3}, {%4,%5,%6,%7}, {%8,%9}, {%0,%1,%2,%3};" \
        : "+f"((d)[0]), "+f"((d)[1]), "+f"((d)[2]), "+f"((d)[3]) \
        : "r"((a)[0]), "r"((a)[1]), "r"((a)[2]), "r"((a)[3]), "r"((b)[0]), "r"((b)[1]))

// smem tile: rows x 32 fp16 (64B/row), XOR swizzle on 16B quarters
__device__ __forceinline__ uint32_t swz(int r, int q) {
    return (uint32_t)(r * 64 + ((q ^ ((r >> 1) & 3)) << 4));
}

__device__ __forceinline__ uint2 pack4h(float4 v) {
    __half2 h01 = __float22half2_rn(make_float2(v.x, v.y));
    __half2 h23 = __float22half2_rn(make_float2(v.z, v.w));
    uint2 r;
    r.x = *reinterpret_cast<uint32_t*>(&h01);
    r.y = *reinterpret_cast<uint32_t*>(&h23);
    return r;
}

__device__ __forceinline__ float gelu_exact(float x) {
    return 0.5f * x * (1.f + erff(x * 0.70710678118654752f));
}

// ---------------- LayerNorm -> fp16, warp-per-row (no barriers) ------------
__global__ void __launch_bounds__(256) ln_kernel(const float* __restrict__ x,
                                                 const float* __restrict__ g,
                                                 const float* __restrict__ b,
                                                 __half* __restrict__ oh)
{
    const int warp = threadIdx.x >> 5, lane = threadIdx.x & 31;
    const int row = blockIdx.x * 8 + warp;
    const float4* xr = (const float4*)(x + (size_t)row * DIM);
    float4 v[8];
    float s = 0.f, ss = 0.f;
    #pragma unroll
    for (int i = 0; i < 8; ++i) {
        v[i] = xr[lane + 32 * i];
        s  += v[i].x + v[i].y + v[i].z + v[i].w;
        ss += v[i].x*v[i].x + v[i].y*v[i].y + v[i].z*v[i].z + v[i].w*v[i].w;
    }
    #pragma unroll
    for (int o = 16; o; o >>= 1) {
        s  += __shfl_xor_sync(0xffffffffu, s,  o);
        ss += __shfl_xor_sync(0xffffffffu, ss, o);
    }
    const float m   = s * (1.f / DIM);
    const float var = ss * (1.f / DIM) - m * m;
    const float r   = rsqrtf(var + 1e-5f);
    uint2* orow = (uint2*)(oh + (size_t)row * DIM);
    #pragma unroll
    for (int i = 0; i < 8; ++i) {
        const float4 gv = ((const float4*)g)[lane + 32 * i];
        const float4 bv = ((const float4*)b)[lane + 32 * i];
        float4 o;
        o.x = (v[i].x - m) * r * gv.x + bv.x;
        o.y = (v[i].y - m) * r * gv.y + bv.y;
        o.z = (v[i].z - m) * r * gv.z + bv.z;
        o.w = (v[i].w - m) * r * gv.w + bv.w;
        orow[lane + 32 * i] = pack4h(o);
    }
}

// ---------------- merged weight transpose: all 6 weights in one launch -----
#define OWELEM ((size_t)1024 * 1024)
__global__ void __launch_bounds__(256) wsplit_all(
    const float* __restrict__ wq, const float* __restrict__ wk,
    const float* __restrict__ wv, const float* __restrict__ wo,
    const float* __restrict__ wff1, const float* __restrict__ wff2,
    __half* __restrict__ wt)
{
    const int idx = blockIdx.x;
    const float* W; __half* Th; int K, N, perm = 0, bx, by;
    if (idx < 1024)      { W = wq;   Th = wt;            K = 1024; N = 1024; bx = idx & 31;  by = idx >> 5; }
    else if (idx < 2048) { W = wk;   Th = wt + OWELEM;   K = 1024; N = 1024; bx = (idx-1024) & 31; by = (idx-1024) >> 5; }
    else if (idx < 3072) { W = wv;   Th = wt + 2*OWELEM; K = 1024; N = 1024; bx = (idx-2048) & 31; by = (idx-2048) >> 5; }
    else if (idx < 4096) { W = wo;   Th = wt + 3*OWELEM; K = 1024; N = 1024; bx = (idx-3072) & 31; by = (idx-3072) >> 5; }
    else if (idx < 8192) { W = wff1; Th = wt + 4*OWELEM; K = 1024; N = 4096; perm = 1; bx = (idx-4096) & 127; by = (idx-4096) >> 7; }
    else                 { W = wff2; Th = wt + 8*OWELEM; K = 2048; N = 1024; bx = (idx-8192) & 31; by = (idx-8192) >> 5; }

    __shared__ float t[32][33];
    const int n0 = bx * 32, k0 = by * 32;
    const int tx = threadIdx.x & 31, ty = threadIdx.x >> 5;
    int sc = n0 + tx;
    if (perm) sc = (sc & 1) ? (sc >> 1) + HIDDEN : (sc >> 1);
    #pragma unroll
    for (int j = 0; j < 4; ++j)
        t[ty + 8*j][tx] = W[(size_t)(k0 + ty + 8*j) * N + sc];
    __syncthreads();
    #pragma unroll
    for (int j = 0; j < 4; ++j) {
        const float v = t[tx][ty + 8*j];
        Th[(size_t)(n0 + ty + 8*j) * K + k0 + tx] = __float2half_rn(v);
    }
}

// ---------------- HMMA GEMM A: 128x256, 8 warps (64x64 tiles), BK=64 -------
// stage = [A sub0 8K | A sub1 8K | B sub0 16K | B sub1 16K] = 48KB, 4 stages.
#define STAGE_BYTES 49152
#define OFF_A  0
#define OFF_B  16384
#define SMEM_MMAGEMM (4 * STAGE_BYTES)   // 196608

template<int EPI, int QKV>
__global__ void __launch_bounds__(256, 1) mma_gemm(
    const __half* __restrict__ A, const __half* __restrict__ B,
    const float* __restrict__ bias, __half* __restrict__ Oh,
    int M, int N, int K)
{
    extern __shared__ char smem_raw[];
    const uint32_t sb = smem_u32(smem_raw);
    const int tid = threadIdx.x, lane = tid & 31, warp = tid >> 5;
    const int bxw = blockIdx.x, by = blockIdx.y;
    const int wm = (warp & 1) << 6;
    const int wn = (warp >> 1) << 6;

    int bx = bxw;
    if (QKV) {
        Oh += (size_t)(bxw >> 2) * M * N;
        bx = bxw & 3;
    }

    const __half* Ag = A + (size_t)(by * 128) * K;
    const __half* Bg = B + (size_t)(bxw * 256) * K;

    const int CHUNKS = K >> 6;
    const int rl = tid >> 2, ql = tid & 3;

    #define LOAD_CHUNK(c, s) do { \
        const uint32_t st_ = sb + (s) * STAGE_BYTES; \
        const int kc_ = (c) << 6; \
        _Pragma("unroll") \
        for (int sub_ = 0; sub_ < 2; ++sub_) { \
            const int gc_ = kc_ + sub_ * 32 + ql * 8; \
            CP_ASYNC16(st_ + OFF_A + sub_ * 8192 + swz(rl, ql), \
                       Ag + (size_t)rl * K + gc_); \
            CP_ASYNC16(st_ + OFF_A + sub_ * 8192 + swz(rl + 64, ql), \
                       Ag + (size_t)(rl + 64) * K + gc_); \
            _Pragma("unroll") \
            for (int i_ = 0; i_ < 4; ++i_) { \
                const int r_ = rl + 64 * i_; \
                CP_ASYNC16(st_ + OFF_B + sub_ * 16384 + swz(r_, ql), \
                           Bg + (size_t)r_ * K + gc_); \
            } \
        } \
    } while (0)

    float acc[4][8][4];
    #pragma unroll
    for (int i = 0; i < 4; ++i)
        #pragma unroll
        for (int j = 0; j < 8; ++j)
            #pragma unroll
            for (int t = 0; t < 4; ++t) acc[i][j][t] = 0.f;

    LOAD_CHUNK(0, 0); CP_COMMIT();
    LOAD_CHUNK(1, 1); CP_COMMIT();
    LOAD_CHUNK(2, 2); CP_COMMIT();

    for (int c = 0; c < CHUNKS; ++c) {
        CP_WAIT2();
        __syncthreads();
        if (c + 3 < CHUNKS) LOAD_CHUNK(c + 3, (c + 3) & 3);
        CP_COMMIT();

        const uint32_t st = sb + (c & 3) * STAGE_BYTES;
        #pragma unroll
        for (int sub = 0; sub < 2; ++sub) {
            const uint32_t sa = st + OFF_A + sub * 8192;
            const uint32_t sB = st + OFF_B + sub * 16384;
            #pragma unroll
            for (int ks = 0; ks < 2; ++ks) {
                uint32_t af[4][4];
                #pragma unroll
                for (int mt = 0; mt < 4; ++mt) {
                    const int row = wm + mt * 16 + (lane & 15);
                    const int q   = (ks << 1) + (lane >> 4);
                    LDSM_X4(af[mt][0], af[mt][1], af[mt][2], af[mt][3],
                            sa + swz(row, q));
                }
                uint32_t bf[8][2];
                #pragma unroll
                for (int np = 0; np < 4; ++np) {
                    const int row = wn + np * 16 + (lane & 7) + ((lane >> 4) << 3);
                    const int q   = (ks << 1) + ((lane >> 3) & 1);
                    uint32_t t0, t1, t2, t3;
                    LDSM_X4(t0, t1, t2, t3, sB + swz(row, q));
                    bf[2*np][0] = t0;   bf[2*np][1] = t1;
                    bf[2*np+1][0] = t2; bf[2*np+1][1] = t3;
                }
                #pragma unroll
                for (int mt = 0; mt < 4; ++mt)
                    #pragma unroll
                    for (int nt = 0; nt < 8; ++nt)
                        MMA16816(acc[mt][nt], af[mt], bf[nt]);
            }
        }
    }

    if (EPI == 3) {
        #pragma unroll
        for (int mt = 0; mt < 4; ++mt) {
            const int gr = by * 128 + wm + mt * 16 + (lane >> 2);
            #pragma unroll
            for (int nt = 0; nt < 8; ++nt) {
                const int col = bx * 256 + wn + nt * 8 + ((lane & 3) << 1);
                const int j = col >> 1;
                const float bv = bias[j];
                const float bg = bias[j + HIDDEN];
                const float h0 = (acc[mt][nt][0] + bv) * gelu_exact(acc[mt][nt][1] + bg);
                const float h1 = (acc[mt][nt][2] + bv) * gelu_exact(acc[mt][nt][3] + bg);
                Oh[(size_t)gr * HIDDEN + j]       = __float2half_rn(h0);
                Oh[(size_t)(gr + 8) * HIDDEN + j] = __float2half_rn(h1);
            }
        }
    } else {
        const float sc = (QKV && (bxw >> 2) == 0) ? 0.125f : 1.0f;
        #pragma unroll
        for (int mt = 0; mt < 4; ++mt) {
            const int gr = by * 128 + wm + mt * 16 + (lane >> 2);
            #pragma unroll
            for (int nt = 0; nt < 8; ++nt) {
                const int col = bx * 256 + wn + nt * 8 + ((lane & 3) << 1);
                __half2 o0 = __float22half2_rn(make_float2(acc[mt][nt][0]*sc, acc[mt][nt][1]*sc));
                __half2 o1 = __float22half2_rn(make_float2(acc[mt][nt][2]*sc, acc[mt][nt][3]*sc));
                *(__half2*)(Oh + (size_t)gr * N + col) = o0;
                *(__half2*)(Oh + (size_t)(gr + 8) * N + col) = o1;
            }
        }
    }
    #undef LOAD_CHUNK
}

// ---------------- HMMA GEMM S: 128x128, 16 warps (32x32 tiles), BK=64 ------
// stage = 32KB, 6 stages (192KB), preload 5, wait_group 4 (4 chunks in flight)
#define STAGE_S 32768
#define SMEM_GEMMS (6 * STAGE_S)   // 196608

__global__ void __launch_bounds__(512, 1) mma_gemm_s(
    const __half* __restrict__ A, const __half* __restrict__ B,
    float* __restrict__ C, const float* __restrict__ bias,
    const float* __restrict__ res, int M, int N, int K)
{
    extern __shared__ char smem_raw[];
    const uint32_t sb = smem_u32(smem_raw);
    const int tid = threadIdx.x, lane = tid & 31, warp = tid >> 5;
    const int bx = blockIdx.x, by = blockIdx.y;
    const int wm = (warp & 3) << 5;
    const int wn = (warp >> 2) << 5;

    const __half* Ag = A + (size_t)(by * 128) * K;
    const __half* Bg = B + (size_t)(bx * 128) * K;

    const int CHUNKS = K >> 6;   // 16 for K=1024, 32 for K=2048
    const int rl = tid >> 2, ql = tid & 3;

    #define LOAD_CHUNK_S(c, s) do { \
        const uint32_t st_ = sb + (s) * STAGE_S; \
        const int kc_ = (c) << 6; \
        _Pragma("unroll") \
        for (int sub_ = 0; sub_ < 2; ++sub_) { \
            const int gc_ = kc_ + sub_ * 32 + ql * 8; \
            const uint32_t o_ = sub_ * 8192 + swz(rl, ql); \
            CP_ASYNC16(st_ + o_,         Ag + (size_t)rl * K + gc_); \
            CP_ASYNC16(st_ + 16384 + o_, Bg + (size_t)rl * K + gc_); \
        } \
    } while (0)

    float acc[2][4][4];
    #pragma unroll
    for (int i = 0; i < 2; ++i)
        #pragma unroll
        for (int j = 0; j < 4; ++j)
            #pragma unroll
            for (int t = 0; t < 4; ++t) acc[i][j][t] = 0.f;

    // stage index = c % 6
    LOAD_CHUNK_S(0, 0); CP_COMMIT();
    LOAD_CHUNK_S(1, 1); CP_COMMIT();
    LOAD_CHUNK_S(2, 2); CP_COMMIT();
    LOAD_CHUNK_S(3, 3); CP_COMMIT();
    LOAD_CHUNK_S(4, 4); CP_COMMIT();

    int stage = 0, nstage = 5;
    for (int c = 0; c < CHUNKS; ++c) {
        CP_WAIT4();
        __syncthreads();
        if (c + 5 < CHUNKS) {
            LOAD_CHUNK_S(c + 5, nstage);
            if (++nstage == 6) nstage = 0;
        }
        CP_COMMIT();

        const uint32_t st = sb + stage * STAGE_S;
        if (++stage == 6) stage = 0;
        #pragma unroll
        for (int sub = 0; sub < 2; ++sub) {
            const uint32_t sa = st + sub * 8192;
            const uint32_t sB = st + 16384 + sub * 8192;
            #pragma unroll
            for (int ks = 0; ks < 2; ++ks) {
                uint32_t af[2][4];
                #pragma unroll
                for (int mt = 0; mt < 2; ++mt) {
                    const int row = wm + mt * 16 + (lane & 15);
                    const int q   = (ks << 1) + (lane >> 4);
                    LDSM_X4(af[mt][0], af[mt][1], af[mt][2], af[mt][3],
                            sa + swz(row, q));
                }
                uint32_t bf[4][2];
                #pragma unroll
                for (int np = 0; np < 2; ++np) {
                    const int row = wn + np * 16 + (lane & 7) + ((lane >> 4) << 3);
                    const int q   = (ks << 1) + ((lane >> 3) & 1);
                    uint32_t t0, t1, t2, t3;
                    LDSM_X4(t0, t1, t2, t3, sB + swz(row, q));
                    bf[2*np][0] = t0;   bf[2*np][1] = t1;
                    bf[2*np+1][0] = t2; bf[2*np+1][1] = t3;
                }
                #pragma unroll
                for (int mt = 0; mt < 2; ++mt)
                    #pragma unroll
                    for (int nt = 0; nt < 4; ++nt)
                        MMA16816(acc[mt][nt], af[mt], bf[nt]);
            }
        }
    }

    #pragma unroll
    for (int mt = 0; mt < 2; ++mt) {
        const int gr = by * 128 + wm + mt * 16 + (lane >> 2);
        #pragma unroll
        for (int nt = 0; nt < 4; ++nt) {
            const int col = bx * 128 + wn + nt * 8 + ((lane & 3) << 1);
            float2 v0 = make_float2(acc[mt][nt][0], acc[mt][nt][1]);
            float2 v1 = make_float2(acc[mt][nt][2], acc[mt][nt][3]);
            const float2 bb = *(const float2*)(bias + col);
            const float2 r0v = *(const float2*)(res + (size_t)gr * N + col);
            const float2 r1v = *(const float2*)(res + (size_t)(gr + 8) * N + col);
            v0.x += bb.x + r0v.x; v0.y += bb.y + r0v.y;
            v1.x += bb.x + r1v.x; v1.y += bb.y + r1v.y;
            *(float2*)(C + (size_t)gr * N + col) = v0;
            *(float2*)(C + (size_t)(gr + 8) * N + col) = v1;
        }
    }
    #undef LOAD_CHUNK_S
}

// ---------------- HMMA sliding-window attention (no-max softmax) -----------
#define AQ 0
#define AK 16384
#define AV 49152
#define AP 81920
#define ABIAS 147456
#define ARED  148480
#define SMEM_ATTN2 150528

__global__ void __launch_bounds__(512, 1) attn_mma(
    const __half* __restrict__ q, const __half* __restrict__ k,
    const __half* __restrict__ v, const float* __restrict__ rel_bias,
    __half* __restrict__ outh)
{
    extern __shared__ char smc[];
    const uint32_t sb = smem_u32(smc);
    const int n = blockIdx.x, h = blockIdx.y, b = blockIdx.z;
    const int tid = threadIdx.x, lane = tid & 31, warp = tid >> 5;
    const size_t row0 = (size_t)b * SEQ + (size_t)n * WIN;

    float* bsf  = (float*)(smc + ABIAS);
    float* redf = (float*)(smc + ARED);

    #pragma unroll
    for (int i = 0; i < 2; ++i) {
        const int row = tid >> 2, Q4 = (tid & 3) + 4 * i;
        const uint32_t off = AQ + (Q4 >> 2) * 8192 + swz(row, Q4 & 3);
        CP_ASYNC16(sb + off, q + (row0 + row) * DIM + h * HD + Q4 * 8);
    }
    #pragma unroll
    for (int i = 0; i < 4; ++i) {
        const int row = (tid >> 2) + 128 * (i >> 1);
        const int Q4 = (tid & 3) + 4 * (i & 1);
        const uint32_t off = AK + (Q4 >> 2) * 16384 + swz(row, Q4 & 3);
        if (n == 0 && row < 128)
            *(uint4*)(smc + off) = make_uint4(0, 0, 0, 0);
        else
            CP_ASYNC16(sb + off, k + (row0 - WIN + row) * DIM + h * HD + Q4 * 8);
    }
    CP_COMMIT();
    #pragma unroll
    for (int i = 0; i < 4; ++i) {
        const int row = (tid >> 3) + 64 * i;
        const int ch  = tid & 7;
        const uint32_t off = AV + (uint32_t)(row * 128 + ((ch ^ (row & 7)) << 4));
        if (n == 0 && row < 128)
            *(uint4*)(smc + off) = make_uint4(0, 0, 0, 0);
        else
            CP_ASYNC16(sb + off, v + (row0 - WIN + row) * DIM + h * HD + ch * 8);
    }
    CP_COMMIT();
    if (tid < 256) bsf[tid] = rel_bias[h * 256 + tid];
    CP_WAIT1();
    __syncthreads();

    const int wm  = (warp & 3) << 5;
    const int wnS = (warp >> 2) << 6;
    const int wnIdx = warp >> 2;

    float acc[2][8][4];
    #pragma unroll
    for (int i = 0; i < 2; ++i)
        #pragma unroll
        for (int j = 0; j < 8; ++j)
            #pragma unroll
            for (int t = 0; t < 4; ++t) acc[i][j][t] = 0.f;

    #pragma unroll
    for (int kc = 0; kc < 2; ++kc)
        #pragma unroll
        for (int ks = 0; ks < 2; ++ks) {
            uint32_t af[2][4];
            #pragma unroll
            for (int mt = 0; mt < 2; ++mt) {
                const int row = wm + mt * 16 + (lane & 15);
                const int qq  = (ks << 1) + (lane >> 4);
                LDSM_X4(af[mt][0], af[mt][1], af[mt][2], af[mt][3],
                        sb + AQ + kc * 8192 + swz(row, qq));
            }
            uint32_t bf[8][2];
            #pragma unroll
            for (int np = 0; np < 4; ++np) {
                const int row = wnS + np * 16 + (lane & 7) + ((lane >> 4) << 3);
                const int qq  = (ks << 1) + ((lane >> 3) & 1);
                uint32_t t0, t1, t2, t3;
                LDSM_X4(t0, t1, t2, t3, sb + AK + kc * 16384 + swz(row, qq));
                bf[2*np][0] = t0;   bf[2*np][1] = t1;
                bf[2*np+1][0] = t2; bf[2*np+1][1] = t3;
            }
            #pragma unroll
            for (int mt = 0; mt < 2; ++mt)
                #pragma unroll
                for (int nt = 0; nt < 8; ++nt)
                    MMA16816(acc[mt][nt], af[mt], bf[nt]);
        }

    const float LOG2E = 1.4426950408889634f;
    float smv[2][2];
    #pragma unroll
    for (int mt = 0; mt < 2; ++mt)
        #pragma unroll
        for (int h2 = 0; h2 < 2; ++h2) {
            const int row = wm + mt * 16 + (lane >> 2) + h2 * 8;
            float rs = 0.f;
            #pragma unroll
            for (int nt = 0; nt < 8; ++nt) {
                const int c0 = wnS + nt * 8;
                const int colp = c0 + ((lane & 3) << 1);
                const int c5 = colp & 31;
                const uint32_t off = AP + (colp >> 5) * 8192 + row * 64 +
                    ((((c5 >> 3)) ^ ((row >> 1) & 3)) << 4) + (c5 & 7) * 2;
                const bool deadtile = (c0 > wm + mt * 16 + 143) ||
                                      (n == 0 && c0 + 8 <= 128);
                if (deadtile) {
                    *(__half2*)(smc + off) = __float2half2_rn(0.f);
                } else {
                    float s0, s1;
                    {
                        const int col = colp;
                        const int dist = row + WIN - col;
                        const bool valid = (dist >= 0) && (n > 0 || col >= WIN);
                        s0 = valid ? (acc[mt][nt][h2*2+0] + bsf[dist]) * LOG2E : -1e30f;
                    }
                    {
                        const int col = colp + 1;
                        const int dist = row + WIN - col;
                        const bool valid = (dist >= 0) && (n > 0 || col >= WIN);
                        s1 = valid ? (acc[mt][nt][h2*2+1] + bsf[dist]) * LOG2E : -1e30f;
                    }
                    const __half2 xh = __float22half2_rn(make_float2(s0, s1));
                    const __half2 ph = h2exp2(xh);
                    *(__half2*)(smc + off) = ph;
                    const float2 pf = __half22float2(ph);
                    rs += pf.x + pf.y;
                }
            }
            smv[mt][h2] = rs;
        }
    #pragma unroll
    for (int mt = 0; mt < 2; ++mt)
        #pragma unroll
        for (int h2 = 0; h2 < 2; ++h2) {
            smv[mt][h2] += __shfl_xor_sync(0xffffffffu, smv[mt][h2], 1);
            smv[mt][h2] += __shfl_xor_sync(0xffffffffu, smv[mt][h2], 2);
        }
    if ((lane & 3) == 0) {
        #pragma unroll
        for (int mt = 0; mt < 2; ++mt)
            #pragma unroll
            for (int h2 = 0; h2 < 2; ++h2)
                redf[wnIdx * 128 + wm + mt * 16 + (lane >> 2) + h2 * 8] = smv[mt][h2];
    }
    CP_WAIT0();
    __syncthreads();

    const int wm2 = (warp & 3) << 5;
    const int wn2 = (warp >> 2) << 4;

    float acc2[2][2][4];
    #pragma unroll
    for (int i = 0; i < 2; ++i)
        #pragma unroll
        for (int j = 0; j < 2; ++j)
            #pragma unroll
            for (int t = 0; t < 4; ++t) acc2[i][j][t] = 0.f;

    for (int kc = 0; kc < 8; ++kc) {
        #pragma unroll
        for (int ks = 0; ks < 2; ++ks) {
            uint32_t af[2][4];
            #pragma unroll
            for (int mt = 0; mt < 2; ++mt) {
                const int row = wm2 + mt * 16 + (lane & 15);
                const int qq  = (ks << 1) + (lane >> 4);
                LDSM_X4(af[mt][0], af[mt][1], af[mt][2], af[mt][3],
                        sb + AP + kc * 8192 + swz(row, qq));
            }
            const int j0 = kc * 32 + ks * 16;
            const int jr = j0 + (lane & 15);
            const int ch = (wn2 >> 3) + (lane >> 4);
            const uint32_t vaddr = AV + (uint32_t)(jr * 128 + ((ch ^ (jr & 7)) << 4));
            uint32_t t0, t1, t2, t3;
            LDSM_X4_TRANS(t0, t1, t2, t3, sb + vaddr);
            uint32_t bf0[2] = { t0, t1 };
            uint32_t bf1[2] = { t2, t3 };
            #pragma unroll
            for (int mt = 0; mt < 2; ++mt) {
                MMA16816(acc2[mt][0], af[mt], bf0);
                MMA16816(acc2[mt][1], af[mt], bf1);
            }
        }
    }

    #pragma unroll
    for (int mt = 0; mt < 2; ++mt) {
        const int rl0 = wm2 + mt * 16 + (lane >> 2);
        const float t0s = redf[rl0] + redf[128 + rl0] + redf[256 + rl0] + redf[384 + rl0];
        const float t1s = redf[rl0 + 8] + redf[128 + rl0 + 8] + redf[256 + rl0 + 8] + redf[384 + rl0 + 8];
        const float i0 = __frcp_rn(t0s);
        const float i1 = __frcp_rn(t1s);
        #pragma unroll
        for (int ntn = 0; ntn < 2; ++ntn) {
            const int col = wn2 + ntn * 8 + ((lane & 3) << 1);
            __half2 o0 = __float22half2_rn(make_float2(acc2[mt][ntn][0]*i0, acc2[mt][ntn][1]*i0));
            __half2 o1 = __float22half2_rn(make_float2(acc2[mt][ntn][2]*i1, acc2[mt][ntn][3]*i1));
            *(__half2*)(outh + (row0 + rl0) * DIM + h * HD + col) = o0;
            *(__half2*)(outh + (row0 + rl0 + 8) * DIM + h * HD + col) = o1;
        }
    }
}

// ---------------- launch ----------------
extern "C" void kernel_launch(void* const* d_in, const int* in_sizes, int n_in,
                              void* d_out, int out_size)
{
    const float* x     = (const float*)d_in[0];
    const float* ln1_g = (const float*)d_in[1];
    const float* ln1_b = (const float*)d_in[2];
    const float* ln2_g = (const float*)d_in[3];
    const float* ln2_b = (const float*)d_in[4];
    const float* wq    = (const float*)d_in[5];
    const float* wk    = (const float*)d_in[6];
    const float* wv    = (const float*)d_in[7];
    const float* wo    = (const float*)d_in[8];
    const float* bo    = (const float*)d_in[9];
    const float* relb  = (const float*)d_in[10];
    const float* wff1  = (const float*)d_in[11];
    const float* bff1  = (const float*)d_in[12];
    const float* wff2  = (const float*)d_in[13];
    const float* bff2  = (const float*)d_in[14];
    float* out = (float*)d_out;

    float *x1;
    __half *lnh, *ath, *hh, *wt, *qkvh;
    cudaGetSymbolAddress((void**)&x1,   g_x1);
    cudaGetSymbolAddress((void**)&lnh,  g_lnh);
    cudaGetSymbolAddress((void**)&ath,  g_ath);
    cudaGetSymbolAddress((void**)&hh,   g_hh);
    cudaGetSymbolAddress((void**)&wt,   g_wt);
    cudaGetSymbolAddress((void**)&qkvh, g_qkvh);

    __half* qh = qkvh;
    __half* kh = qkvh + (size_t)MROWS * DIM;
    __half* vh = qkvh + (size_t)2 * MROWS * DIM;

    cudaFuncSetAttribute(attn_mma, cudaFuncAttributeMaxDynamicSharedMemorySize, SMEM_ATTN2);
    cudaFuncSetAttribute((mma_gemm<4,1>), cudaFuncAttributeMaxDynamicSharedMemorySize, SMEM_MMAGEMM);
    cudaFuncSetAttribute((mma_gemm<3,0>), cudaFuncAttributeMaxDynamicSharedMemorySize, SMEM_MMAGEMM);
    cudaFuncSetAttribute(mma_gemm_s, cudaFuncAttributeMaxDynamicSharedMemorySize, SMEM_GEMMS);

    __half *tq = wt;
    __half *to = wt + 3*OWELEM;
    __half *t1 = wt + 4*OWELEM;
    __half *t2 = wt + 8*OWELEM;

    wsplit_all<<<10240, 256>>>(wq, wk, wv, wo, wff1, wff2, wt);

    ln_kernel<<<MROWS/8, 256>>>(x, ln1_g, ln1_b, lnh);
    mma_gemm<4,1><<<dim3(12, 128), 256, SMEM_MMAGEMM>>>(lnh, tq,
        nullptr, qkvh, MROWS, 1024, 1024);
    attn_mma<<<dim3(NW, HEADS, BATCH), 512, SMEM_ATTN2>>>(qh, kh, vh, relb, ath);
    mma_gemm_s<<<dim3(8, 128), 512, SMEM_GEMMS>>>(ath, to, x1,
        bo, x, MROWS, 1024, 1024);
    ln_kernel<<<MROWS/8, 256>>>(x1, ln2_g, ln2_b, lnh);
    mma_gemm<3,0><<<dim3(16, 128), 256, SMEM_MMAGEMM>>>(lnh, t1,
        bff1, hh, MROWS, 4096, 1024);
    mma_gemm_s<<<dim3(8, 128), 512, SMEM_GEMMS>>>(hh, t2, out,
        bff2, x1, MROWS, 1024, 2048);
}